// round 7
// baseline (speedup 1.0000x reference)
#include <cuda_runtime.h>
#include <cstdint>

// PNN_62156766707845 — GB300 sm_103a, round 7
// bf16 2-term split, m16n8k16 mma.sync. 4 warps/CTA, warp tile 32x32,
// 48KB SMEM (double buffer, lin weights staged into dead buffer at epilogue),
// 4 CTAs/SM target, prefetch distance 2.

#define FDIM   39
#define EDIM   16
#define VDIM   100000
#define MTILE  64
#define NTHR   128
#define NCHUNK 20            // K = 640 (20 x 32)

#define RSF     24           // row stride floats (96B), conflict-free LDS.64
#define PLANE_F (64 * RSF)   // 1536
#define BUF_F   (4 * PLANE_F)   // 6144 floats = 24KB
#define SMEM_BYTES (2 * BUF_F * 4)   // 49152 = 48KB
#define XS_S    66

__device__ __forceinline__ uint32_t packbf(float lo, float hi) {
    uint32_t r;
    asm("cvt.rn.bf16x2.f32 %0, %1, %2;" : "=r"(r) : "f"(hi), "f"(lo));
    return r;
}
__device__ __forceinline__ float f_lo(uint32_t u) { return __uint_as_float(u << 16); }
__device__ __forceinline__ float f_hi(uint32_t u) { return __uint_as_float(u & 0xFFFF0000u); }

__device__ __forceinline__ void mma16(float* c, const uint32_t* a, const uint32_t* b) {
    asm volatile(
        "mma.sync.aligned.m16n8k16.row.col.f32.bf16.bf16.f32 "
        "{%0,%1,%2,%3}, {%4,%5,%6,%7}, {%8,%9}, {%0,%1,%2,%3};"
        : "+f"(c[0]), "+f"(c[1]), "+f"(c[2]), "+f"(c[3])
        : "r"(a[0]), "r"(a[1]), "r"(a[2]), "r"(a[3]), "r"(b[0]), "r"(b[1]));
}

// 16 floats (k 0..15) -> permuted hi/lo bf16x2, 32B store per plane.
__device__ __forceinline__ void cvt_store16(float* hdst, float* ldst, const float* x) {
    uint32_t hu[8], lu[8];
#pragma unroll
    for (int j = 0; j < 4; j++) {
        float a0 = x[2 * j],     a1 = x[2 * j + 1];
        float b0 = x[2 * j + 8], b1 = x[2 * j + 9];
        uint32_t ha = packbf(a0, a1);
        uint32_t hb = packbf(b0, b1);
        hu[2 * j]     = ha;
        hu[2 * j + 1] = hb;
        lu[2 * j]     = packbf(a0 - f_lo(ha), a1 - f_hi(ha));
        lu[2 * j + 1] = packbf(b0 - f_lo(hb), b1 - f_hi(hb));
    }
    *(uint4*)(hdst)     = make_uint4(hu[0], hu[1], hu[2], hu[3]);
    *(uint4*)(hdst + 4) = make_uint4(hu[4], hu[5], hu[6], hu[7]);
    *(uint4*)(ldst)     = make_uint4(lu[0], lu[1], lu[2], lu[3]);
    *(uint4*)(ldst + 4) = make_uint4(lu[4], lu[5], lu[6], lu[7]);
}

extern "C" __global__ void __launch_bounds__(NTHR, 4)
pnn_kernel(const int* __restrict__ Xi, const float* __restrict__ Xv,
           const float* __restrict__ emb,
           const float* __restrict__ w_first, const float* __restrict__ w_inner,
           const float* __restrict__ lin1W, const float* __restrict__ lin1b,
           const float* __restrict__ lin2W, const float* __restrict__ lin2b,
           const float* __restrict__ lastW, const float* __restrict__ lastb,
           float* __restrict__ out, int B)
{
    extern __shared__ float sm[];

    const int tid  = threadIdx.x;
    const int wid  = tid >> 5;
    const int lane = tid & 31;
    const int qr   = lane >> 2;
    const int qc   = lane & 3;
    const int RM   = (wid & 1) * 32;
    const int CN   = (wid >> 1) * 32;

    // staging roles: warps 0-1 -> A (row = tid, 2 slots); warps 2-3 -> B (n, 2 slots)
    const bool isA  = tid < 64;
    const int  srow = isA ? tid : (tid - 64);
    const int  grow = blockIdx.x * MTILE + srow;
    const long long rowbase = (long long)((grow < B) ? grow : 0) * FDIM;
    const float* bsrc_base = (srow < 32)
        ? (w_first + (long long)srow * FDIM * EDIM)
        : (w_inner + (long long)(srow - 32) * FDIM * EDIM);

    float pf[2][16]; float pxv[2];

    // ---- prologue: stage chunk 0 directly, prefetch chunk 1 ----
    if (isA) {
#pragma unroll
        for (int s = 0; s < 2; s++) {
            int f = s;
            int idx = Xi[rowbase + f];
            float xv = Xv[rowbase + f];
            const float4* p = (const float4*)emb + ((long long)f * VDIM + idx) * 4;
            float x[16];
            *(float4*)(x) = p[0]; *(float4*)(x + 4) = p[1];
            *(float4*)(x + 8) = p[2]; *(float4*)(x + 12) = p[3];
#pragma unroll
            for (int j = 0; j < 16; j++) x[j] *= xv;
            float* hd = sm + srow * RSF + s * 8;
            cvt_store16(hd, hd + PLANE_F, x);
        }
#pragma unroll
        for (int s = 0; s < 2; s++) {
            int f = 2 + s;
            int idx = Xi[rowbase + f];
            pxv[s] = Xv[rowbase + f];
            const float4* p = (const float4*)emb + ((long long)f * VDIM + idx) * 4;
            *(float4*)(pf[s]) = p[0]; *(float4*)(pf[s] + 4) = p[1];
            *(float4*)(pf[s] + 8) = p[2]; *(float4*)(pf[s] + 12) = p[3];
        }
    } else {
#pragma unroll
        for (int s = 0; s < 2; s++) {
            const float4* p = (const float4*)(bsrc_base + (long long)s * EDIM);
            float x[16];
            *(float4*)(x) = p[0]; *(float4*)(x + 4) = p[1];
            *(float4*)(x + 8) = p[2]; *(float4*)(x + 12) = p[3];
            float* hd = sm + 2 * PLANE_F + srow * RSF + s * 8;
            cvt_store16(hd, hd + PLANE_F, x);
        }
#pragma unroll
        for (int s = 0; s < 2; s++) {
            const float4* p = (const float4*)(bsrc_base + (long long)(2 + s) * EDIM);
            *(float4*)(pf[s]) = p[0]; *(float4*)(pf[s] + 4) = p[1];
            *(float4*)(pf[s] + 8) = p[2]; *(float4*)(pf[s] + 12) = p[3];
        }
    }
    __syncthreads();

    float acc[2][4][4];
#pragma unroll
    for (int mt = 0; mt < 2; mt++)
#pragma unroll
        for (int nt = 0; nt < 4; nt++)
#pragma unroll
            for (int c = 0; c < 4; c++) acc[mt][nt][c] = 0.f;

    for (int i = 0; i < NCHUNK; i++) {
        // 1) convert+store chunk i+1 into buf (i+1)&1
        if (i + 1 < NCHUNK) {
            float* base = sm + ((i + 1) & 1) * BUF_F;
            if (isA) {
#pragma unroll
                for (int s = 0; s < 2; s++) {
                    float x[16];
#pragma unroll
                    for (int j = 0; j < 16; j++) x[j] = pf[s][j] * pxv[s];
                    float* hd = base + srow * RSF + s * 8;
                    cvt_store16(hd, hd + PLANE_F, x);
                }
            } else {
#pragma unroll
                for (int s = 0; s < 2; s++) {
                    float* hd = base + 2 * PLANE_F + srow * RSF + s * 8;
                    cvt_store16(hd, hd + PLANE_F, pf[s]);
                }
            }
        }
        // 2) LDG chunk i+2 into prefetch regs
        if (i + 2 < NCHUNK) {
#pragma unroll
            for (int s = 0; s < 2; s++) {
                const int f = 2 * (i + 2) + s;
                if (isA) {
                    if (f < FDIM) {
                        int idx = Xi[rowbase + f];
                        pxv[s] = Xv[rowbase + f];
                        const float4* p = (const float4*)emb + ((long long)f * VDIM + idx) * 4;
                        *(float4*)(pf[s]) = p[0]; *(float4*)(pf[s] + 4) = p[1];
                        *(float4*)(pf[s] + 8) = p[2]; *(float4*)(pf[s] + 12) = p[3];
                    } else {
                        pxv[s] = 0.f;
#pragma unroll
                        for (int j = 0; j < 16; j++) pf[s][j] = 0.f;
                    }
                } else {
                    if (f < FDIM) {
                        const float4* p = (const float4*)(bsrc_base + (long long)f * EDIM);
                        *(float4*)(pf[s]) = p[0]; *(float4*)(pf[s] + 4) = p[1];
                        *(float4*)(pf[s] + 8) = p[2]; *(float4*)(pf[s] + 12) = p[3];
                    } else {
#pragma unroll
                        for (int j = 0; j < 16; j++) pf[s][j] = 0.f;
                    }
                }
            }
        }

        // 3) compute chunk i from buf i&1
        {
            const float* base = sm + (i & 1) * BUF_F;
            const float* Ah = base;
            const float* Al = base + PLANE_F;
            const float* Bh = base + 2 * PLANE_F;
            const float* Bl = base + 3 * PLANE_F;
#pragma unroll
            for (int kt = 0; kt < 2; kt++) {
                const int ko = kt * 8 + 2 * qc;
                uint32_t ah[2][4], al[2][4], bh[4][2], bl[4][2];
#pragma unroll
                for (int mt = 0; mt < 2; mt++) {
                    const int ra = (RM + mt * 16 + qr) * RSF + ko;
                    const int rb = ra + 8 * RSF;
                    uint2 uh = *(const uint2*)(Ah + ra);
                    uint2 vh = *(const uint2*)(Ah + rb);
                    uint2 ul = *(const uint2*)(Al + ra);
                    uint2 vl = *(const uint2*)(Al + rb);
                    ah[mt][0] = uh.x; ah[mt][1] = vh.x; ah[mt][2] = uh.y; ah[mt][3] = vh.y;
                    al[mt][0] = ul.x; al[mt][1] = vl.x; al[mt][2] = ul.y; al[mt][3] = vl.y;
                }
#pragma unroll
                for (int nt = 0; nt < 4; nt++) {
                    const int nb = (CN + nt * 8 + qr) * RSF + ko;
                    uint2 wh = *(const uint2*)(Bh + nb);
                    uint2 wl = *(const uint2*)(Bl + nb);
                    bh[nt][0] = wh.x; bh[nt][1] = wh.y;
                    bl[nt][0] = wl.x; bl[nt][1] = wl.y;
                }
                // pass-major ordering: 8 independent MMAs between same-acc reuse
#pragma unroll
                for (int nt = 0; nt < 4; nt++) {
                    mma16(acc[0][nt], ah[0], bh[nt]);
                    mma16(acc[1][nt], ah[1], bh[nt]);
                }
#pragma unroll
                for (int nt = 0; nt < 4; nt++) {
                    mma16(acc[0][nt], ah[0], bl[nt]);
                    mma16(acc[1][nt], ah[1], bl[nt]);
                }
#pragma unroll
                for (int nt = 0; nt < 4; nt++) {
                    mma16(acc[0][nt], al[0], bh[nt]);
                    mma16(acc[1][nt], al[1], bh[nt]);
                }
            }
        }
        __syncthreads();
    }

    // ---- epilogue: buffers dead. xs at sm[0..4224), lin at sm[4224..6369) ----
    float* xs  = sm;
    float* l1  = sm + 4224;
    float* l2  = l1 + 1024;
    float* bb1 = l2 + 1024;
    float* bb2 = bb1 + 32;
    float* lw  = bb2 + 32;
    float* lb  = lw + 32;

    for (int i = tid; i < 1024; i += NTHR) { l1[i] = lin1W[i]; l2[i] = lin2W[i]; }
    if (tid < 32) { bb1[tid] = lin1b[tid]; bb2[tid] = lin2b[tid]; lw[tid] = lastW[tid]; }
    if (tid == 0) lb[0] = lastb[0];

#pragma unroll
    for (int mt = 0; mt < 2; mt++) {
        const int r0 = RM + mt * 16 + qr;
#pragma unroll
        for (int nt = 0; nt < 4; nt++) {
            const int n = CN + nt * 8 + 2 * qc;
            *(float2*)(xs + r0 * XS_S + n)       = make_float2(acc[mt][nt][0], acc[mt][nt][1]);
            *(float2*)(xs + (r0 + 8) * XS_S + n) = make_float2(acc[mt][nt][2], acc[mt][nt][3]);
        }
    }
    __syncthreads();

    // MLP: 2 threads per row (128 threads, 64 rows)
    {
        const int rr = tid >> 1;
        const int half = tid & 1;
        float* xr = xs + rr * XS_S;

        float x[32];
#pragma unroll
        for (int d = 0; d < 32; d++) {
            float s = xr[32 + d];
            x[d] = fmaf(s, s, xr[d]);
        }
        __syncwarp();

        float h[16];
#pragma unroll
        for (int jl = 0; jl < 16; jl++) {
            const int j = half * 16 + jl;
            float a = bb1[j];
            const float* wrow = l1 + j * 32;
#pragma unroll
            for (int d = 0; d < 32; d++) a = fmaf(wrow[d], x[d], a);
            h[jl] = fmaxf(a, 0.0f);
        }
        __syncwarp();
#pragma unroll
        for (int jl = 0; jl < 16; jl++) xr[half * 16 + jl] = h[jl];
        __syncwarp();

        float h1[32];
#pragma unroll
        for (int d = 0; d < 32; d++) h1[d] = xr[d];

        float h2[16];
#pragma unroll
        for (int jl = 0; jl < 16; jl++) {
            const int j = half * 16 + jl;
            float a = bb2[j];
            const float* wrow = l2 + j * 32;
#pragma unroll
            for (int d = 0; d < 32; d++) a = fmaf(wrow[d], h1[d], a);
            h2[jl] = fmaxf(a, 0.0f);
        }
        __syncwarp();
#pragma unroll
        for (int jl = 0; jl < 16; jl++) xr[half * 16 + jl] = h2[jl];
        __syncwarp();

        if (half == 0) {
            const int g = blockIdx.x * MTILE + rr;
            if (g < B) {
                float a = lb[0];
#pragma unroll
                for (int j = 0; j < 32; j++) a = fmaf(lw[j], xr[j], a);
                out[g] = a;
            }
        }
    }
}

extern "C" void kernel_launch(void* const* d_in, const int* in_sizes, int n_in,
                              void* d_out, int out_size)
{
    const int*   Xi      = (const int*)d_in[0];
    const float* Xv      = (const float*)d_in[1];
    const float* emb     = (const float*)d_in[2];
    const float* w_first = (const float*)d_in[3];
    const float* w_inner = (const float*)d_in[4];
    const float* lin1W   = (const float*)d_in[5];
    const float* lin1b   = (const float*)d_in[6];
    const float* lin2W   = (const float*)d_in[7];
    const float* lin2b   = (const float*)d_in[8];
    const float* lastW   = (const float*)d_in[9];
    const float* lastb   = (const float*)d_in[10];
    float* out = (float*)d_out;

    const int B = in_sizes[0] / FDIM;

    cudaFuncSetAttribute(pnn_kernel, cudaFuncAttributeMaxDynamicSharedMemorySize,
                         SMEM_BYTES);

    const int grid = (B + MTILE - 1) / MTILE;
    pnn_kernel<<<grid, NTHR, SMEM_BYTES>>>(Xi, Xv, emb, w_first, w_inner,
                                           lin1W, lin1b, lin2W, lin2b,
                                           lastW, lastb, out, B);
}